// round 7
// baseline (speedup 1.0000x reference)
#include <cuda_runtime.h>
#include <math.h>
#include <stdint.h>

#define NN 100000
#define EE 800000
#define ENN (EE + NN)
#define SZ ((size_t)NN * 128)

// ---------------- device scratch pool (~2.18 GB; must stay << 4GB) ----------
static __device__ float g_fpool[545000000];
static __device__ int   g_ipool[2400000];

// Region A (307.2M floats) -- three disjoint lifetimes:
//   GAT phase : X0[2*SZ] | MEAN[SZ] | XH[4*SZ]            (89.6M)
//   LSTM phase: G4[4*NN*768]                               (307.2M)
//   head phase: JK[2*SZ] | SQ[2*SZ] | O4[4*SZ]             (102.4M)
#define OFF_A    ((size_t)0)
#define SZ_A     ((size_t)4 * NN * 768)
#define OFF_XS   (OFF_A + SZ_A)                      // 6*SZ
#define OFF_HC   (OFF_XS + 6 * SZ)                   // 4*NN*192
#define OFF_CST  (OFF_HC + (size_t)4 * NN * 192)     // 4*NN*192
#define OFF_LOG  (OFF_CST + (size_t)4 * NN * 192)    // 12*NN
#define OFF_AS   (OFF_LOG + (size_t)12 * NN)         // 2*NN*2
#define OFF_AD   (OFF_AS + (size_t)2 * NN * 2)       // 2*NN*2
#define OFF_WIHT (OFF_AD + (size_t)2 * NN * 2)       // 4*98304
#define OFF_WHHT (OFF_WIHT + (size_t)4 * 98304)      // 4*147456
#define OFF_BSUM (OFF_WHHT + (size_t)4 * 147456)     // 4*768

#define IOFF_PTR 0
#define IOFF_CUR (2 * (NN + 1))
#define IOFF_COL (IOFF_CUR + 2 * NN)

// ---------------- helpers ----------------------------------------------------
__device__ __forceinline__ float warp_sum(float v) {
    #pragma unroll
    for (int o = 16; o; o >>= 1) v += __shfl_xor_sync(0xffffffffu, v, o);
    return v;
}
__device__ __forceinline__ float warp_max(float v) {
    #pragma unroll
    for (int o = 16; o; o >>= 1) v = fmaxf(v, __shfl_xor_sync(0xffffffffu, v, o));
    return v;
}
__device__ __forceinline__ float sigm(float x) { return 1.f / (1.f + expf(-x)); }
__device__ __forceinline__ uint32_t f2tf(float x) {
    uint32_t r;
    asm("cvt.rna.tf32.f32 %0, %1;" : "=r"(r) : "f"(x));
    return r;
}
__device__ __forceinline__ void mma8(float* c, const uint32_t* a, uint32_t b0, uint32_t b1) {
    asm volatile("mma.sync.aligned.m16n8k8.row.col.f32.tf32.tf32.f32 "
                 "{%0,%1,%2,%3},{%4,%5,%6,%7},{%8,%9},{%0,%1,%2,%3};"
                 : "+f"(c[0]), "+f"(c[1]), "+f"(c[2]), "+f"(c[3])
                 : "r"(a[0]), "r"(a[1]), "r"(a[2]), "r"(a[3]), "r"(b0), "r"(b1));
}

// ---------------- node feature build ----------------------------------------
__global__ void k_build_x(const int* __restrict__ x_idx, const float* __restrict__ x_flt,
                          const float* __restrict__ emb_aa, const float* __restrict__ emb_ss,
                          float* __restrict__ x0l, float* __restrict__ x0r) {
    int n = blockIdx.x, t = threadIdx.x;
    int ai = x_idx[2 * n], si = x_idx[2 * n + 1];
    float vl, vr;
    if (t < 123) {
        vl = emb_aa[(size_t)ai * 123 + t] + emb_ss[(size_t)si * 123 + t];
        vr = emb_aa[(size_t)(26 + ai) * 123 + t] + emb_ss[(size_t)(3 + si) * 123 + t];
    } else {
        float f = x_flt[(size_t)n * 5 + (t - 123)];
        vl = f; vr = f;
    }
    x0l[(size_t)n * 128 + t] = vl;
    x0r[(size_t)n * 128 + t] = vr;
}

// ---------------- CSR build (batched over 2 branches) ------------------------
__global__ void k_fill_int(int* p, int v, int n) {
    int i = blockIdx.x * blockDim.x + threadIdx.x;
    if (i < n) p[i] = v;
}
__global__ void k_hist2(const int* __restrict__ e0, const int* __restrict__ e1, int* cnt) {
    int b = blockIdx.y;
    int e = blockIdx.x * blockDim.x + threadIdx.x;
    if (e >= EE) return;
    const int* d = (b ? e1 : e0) + EE;
    atomicAdd(&cnt[b * NN + d[e]], 1);
}
__global__ void k_scan2(const int* __restrict__ cntb, int* __restrict__ ptrb) {
    __shared__ int sh[1024];
    int br = blockIdx.x;
    const int* cnt = cntb + br * NN;
    int* indptr = ptrb + br * (NN + 1);
    int t = threadIdx.x;
    int chunk = (NN + 1023) >> 10;
    int s0 = t * chunk, s1 = s0 + chunk; if (s1 > NN) s1 = NN;
    int sum = 0;
    for (int i = s0; i < s1; i++) sum += cnt[i];
    sh[t] = sum;
    __syncthreads();
    for (int off = 1; off < 1024; off <<= 1) {
        int v = (t >= off) ? sh[t - off] : 0;
        __syncthreads();
        sh[t] += v;
        __syncthreads();
    }
    int run = (t == 0) ? 0 : sh[t - 1];
    if (t == 0) indptr[0] = 0;
    for (int i = s0; i < s1; i++) { run += cnt[i]; indptr[i + 1] = run; }
}
__global__ void k_initcur(const int* __restrict__ ptrb, int* __restrict__ curb) {
    int i = blockIdx.x * blockDim.x + threadIdx.x;
    if (i >= 2 * NN) return;
    int b = i >= NN;
    curb[i] = ptrb[b * (NN + 1) + (i - b * NN)];
}
__global__ void k_scatter2(const int* __restrict__ e0, const int* __restrict__ e1,
                           int* curb, int* colb) {
    int b = blockIdx.y;
    int e = blockIdx.x * blockDim.x + threadIdx.x;
    if (e >= ENN) return;
    const int* ei = b ? e1 : e0;
    int s, d;
    if (e < EE) { s = ei[e]; d = ei[EE + e]; } else { s = e - EE; d = s; }
    int pos = atomicAdd(&curb[b * NN + d], 1);
    colb[b * ENN + pos] = s;
}

// ---------------- weight transpose / bias sum (batched grid.y) ---------------
__global__ void k_transpose(const float* __restrict__ W, float* __restrict__ WT, int R, int C) {
    int z = blockIdx.y;
    const float* Wz = W + (size_t)z * R * C;
    float* WTz = WT + (size_t)z * R * C;
    int idx = blockIdx.x * blockDim.x + threadIdx.x;
    if (idx >= R * C) return;
    int r = idx / C, c = idx - r * C;
    WTz[(size_t)c * R + r] = Wz[idx];
}
__global__ void k_bsum(const float* __restrict__ a, const float* __restrict__ b, float* o, int n) {
    int i = blockIdx.x * blockDim.x + threadIdx.x;
    if (i < n) o[i] = a[i] + b[i];
}
__global__ void k_mean(const float* __restrict__ a, const float* __restrict__ b, float* o, size_t n) {
    size_t i = (size_t)blockIdx.x * blockDim.x + threadIdx.x;
    if (i < n) o[i] = 0.5f * (a[i] + b[i]);
}

// ---------------- batched TF32 tensor-core GEMM ------------------------------
// C[z] = A[z][MxK] @ B[z][KxN] (+bias[z]) (+=C). blockIdx.z selects problem.
// SPLIT=1: hi/lo split-tf32 (3 MMAs, ~fp32), BK=16. SPLIT=0: BK=32.
// 8 warps (2x4), warp tile 64x32, register-staged global prefetch.
struct Ptrs12 {
    const float* A[12];
    const float* B[12];
    const float* Bias[12];
    float* C[12];
};

template<int SPLIT>
__global__ __launch_bounds__(256) void k_gemm(
    Ptrs12 P, int M, int Nc, int K, int doAcc) {
    constexpr int BK = SPLIT ? 16 : 32;
    __shared__ uint32_t Ash[BK][132];
    __shared__ uint32_t Bsh[BK][136];
    __shared__ uint32_t Asl[SPLIT ? BK : 1][SPLIT ? 132 : 1];
    __shared__ uint32_t Bsl[SPLIT ? BK : 1][SPLIT ? 136 : 1];

    const int z = blockIdx.z;
    const float* __restrict__ A = P.A[z];
    const float* __restrict__ B = P.B[z];
    const float* __restrict__ bias = P.Bias[z];
    float* __restrict__ C = P.C[z];

    const int bm = blockIdx.x * 128, bn = blockIdx.y * 128;
    const int tid = threadIdx.x, lane = tid & 31, w = tid >> 5;
    const int wm = (w & 1) * 64, wn = (w >> 1) * 32;
    const int gid = lane >> 2, t4 = lane & 3;

    const int arow = tid >> 1, akh = (tid & 1) * (BK / 2);
    const int bkr = (BK == 32) ? (tid >> 3) : (tid >> 4);
    const int bnq = (BK == 32) ? (tid & 7) * 16 : (tid & 15) * 8;
    const bool arow_ok = (bm + arow) < M;

    float sa[BK / 2], sb[BK / 2];

    #pragma unroll
    for (int q = 0; q < BK / 8; q++) {
        float4 v = make_float4(0.f, 0.f, 0.f, 0.f);
        if (arow_ok) v = *(const float4*)(A + (size_t)(bm + arow) * K + akh + 4 * q);
        sa[4 * q] = v.x; sa[4 * q + 1] = v.y; sa[4 * q + 2] = v.z; sa[4 * q + 3] = v.w;
        float4 u = *(const float4*)(B + (size_t)bkr * Nc + bn + bnq + 4 * q);
        sb[4 * q] = u.x; sb[4 * q + 1] = u.y; sb[4 * q + 2] = u.z; sb[4 * q + 3] = u.w;
    }

    float acc[4][4][4];
    #pragma unroll
    for (int i = 0; i < 4; i++)
        #pragma unroll
        for (int j = 0; j < 4; j++)
            #pragma unroll
            for (int r = 0; r < 4; r++) acc[i][j][r] = 0.f;

    for (int k0 = 0; k0 < K; k0 += BK) {
        #pragma unroll
        for (int j = 0; j < BK / 2; j++) {
            uint32_t hi = f2tf(sa[j]);
            Ash[akh + j][arow] = hi;
            if (SPLIT) Asl[akh + j][arow] = f2tf(sa[j] - __uint_as_float(hi));
        }
        #pragma unroll
        for (int q = 0; q < BK / 8; q++) {
            uint32_t hh[4], ll[4];
            #pragma unroll
            for (int j = 0; j < 4; j++) {
                hh[j] = f2tf(sb[4 * q + j]);
                if (SPLIT) ll[j] = f2tf(sb[4 * q + j] - __uint_as_float(hh[j]));
            }
            *(uint4*)&Bsh[bkr][bnq + 4 * q] = *(uint4*)hh;
            if (SPLIT) *(uint4*)&Bsl[bkr][bnq + 4 * q] = *(uint4*)ll;
        }
        __syncthreads();

        if (k0 + BK < K) {
            #pragma unroll
            for (int q = 0; q < BK / 8; q++) {
                float4 v = make_float4(0.f, 0.f, 0.f, 0.f);
                if (arow_ok) v = *(const float4*)(A + (size_t)(bm + arow) * K + k0 + BK + akh + 4 * q);
                sa[4 * q] = v.x; sa[4 * q + 1] = v.y; sa[4 * q + 2] = v.z; sa[4 * q + 3] = v.w;
                float4 u = *(const float4*)(B + (size_t)(k0 + BK + bkr) * Nc + bn + bnq + 4 * q);
                sb[4 * q] = u.x; sb[4 * q + 1] = u.y; sb[4 * q + 2] = u.z; sb[4 * q + 3] = u.w;
            }
        }

        #pragma unroll
        for (int ks = 0; ks < BK; ks += 8) {
            uint32_t ah[4][4], al[SPLIT ? 4 : 1][SPLIT ? 4 : 1];
            #pragma unroll
            for (int mt = 0; mt < 4; mt++) {
                int m = wm + mt * 16 + gid;
                ah[mt][0] = Ash[ks + t4][m];
                ah[mt][1] = Ash[ks + t4][m + 8];
                ah[mt][2] = Ash[ks + t4 + 4][m];
                ah[mt][3] = Ash[ks + t4 + 4][m + 8];
                if (SPLIT) {
                    al[mt][0] = Asl[ks + t4][m];
                    al[mt][1] = Asl[ks + t4][m + 8];
                    al[mt][2] = Asl[ks + t4 + 4][m];
                    al[mt][3] = Asl[ks + t4 + 4][m + 8];
                }
            }
            #pragma unroll
            for (int nt = 0; nt < 4; nt++) {
                int nn = wn + nt * 8 + gid;
                uint32_t b0 = Bsh[ks + t4][nn];
                uint32_t b1 = Bsh[ks + t4 + 4][nn];
                uint32_t b0l = 0, b1l = 0;
                if (SPLIT) { b0l = Bsl[ks + t4][nn]; b1l = Bsl[ks + t4 + 4][nn]; }
                #pragma unroll
                for (int mt = 0; mt < 4; mt++) {
                    mma8(acc[mt][nt], ah[mt], b0, b1);
                    if (SPLIT) {
                        mma8(acc[mt][nt], ah[mt], b0l, b1l);
                        mma8(acc[mt][nt], al[mt], b0, b1);
                    }
                }
            }
        }
        __syncthreads();
    }

    #pragma unroll
    for (int mt = 0; mt < 4; mt++) {
        int r0 = bm + wm + mt * 16 + gid;
        #pragma unroll
        for (int nt = 0; nt < 4; nt++) {
            int c = bn + wn + nt * 8 + 2 * t4;
            float bx = 0.f, by = 0.f;
            if (bias) { bx = bias[c]; by = bias[c + 1]; }
            if (r0 < M) {
                float* p = C + (size_t)r0 * Nc + c;
                float2 v = make_float2(acc[mt][nt][0] + bx, acc[mt][nt][1] + by);
                if (doAcc) { float2 o = *(float2*)p; v.x += o.x; v.y += o.y; }
                *(float2*)p = v;
            }
            if (r0 + 8 < M) {
                float* p = C + (size_t)(r0 + 8) * Nc + c;
                float2 v = make_float2(acc[mt][nt][2] + bx, acc[mt][nt][3] + by);
                if (doAcc) { float2 o = *(float2*)p; v.x += o.x; v.y += o.y; }
                *(float2*)p = v;
            }
        }
    }
}

// ---------------- GAT attention scores (batched over branch) -----------------
__global__ void k_att(const float* __restrict__ xhb, const float* __restrict__ att_src,
                      const float* __restrict__ att_dst, int layer,
                      float* __restrict__ asb, float* __restrict__ adb, int N) {
    int b = blockIdx.y;
    int w = (blockIdx.x * blockDim.x + threadIdx.x) >> 5;
    int lane = threadIdx.x & 31;
    if (w >= N) return;
    const float* row = xhb + (size_t)b * NN * 256 + (size_t)w * 256;
    const float* asv = att_src + (size_t)(b * 3 + layer) * 256;
    const float* adv = att_dst + (size_t)(b * 3 + layer) * 256;
    float s0 = 0, d0 = 0, s1 = 0, d1 = 0;
    #pragma unroll
    for (int c = lane; c < 128; c += 32) {
        float v0 = row[c], v1 = row[128 + c];
        s0 += v0 * asv[c];       d0 += v0 * adv[c];
        s1 += v1 * asv[128 + c]; d1 += v1 * adv[128 + c];
    }
    s0 = warp_sum(s0); d0 = warp_sum(d0); s1 = warp_sum(s1); d1 = warp_sum(d1);
    if (lane == 0) {
        float* asrc = asb + (size_t)b * NN * 2;
        float* adst = adb + (size_t)b * NN * 2;
        asrc[2 * w] = s0; asrc[2 * w + 1] = s1;
        adst[2 * w] = d0; adst[2 * w + 1] = d1;
    }
}

// ---------------- GAT softmax+aggregate (warp/node, batched over branch) -----
__global__ void k_aggr(const int* __restrict__ ptrb, const int* __restrict__ colb,
                       const float* __restrict__ xhb, const float* __restrict__ asb,
                       const float* __restrict__ adb, const float* __restrict__ conv_b,
                       int layer, const float* __restrict__ meanb,
                       float* __restrict__ xsb, int N) {
    int b = blockIdx.y;
    int w = (blockIdx.x * blockDim.x + threadIdx.x) >> 5;
    int lane = threadIdx.x & 31;
    if (w >= N) return;
    const int* indptr = ptrb + b * (NN + 1);
    const int* colsrc = colb + (size_t)b * ENN;
    const float* xh = xhb + (size_t)b * NN * 256;
    const float* asrc = asb + (size_t)b * NN * 2;
    const float* adst = adb + (size_t)b * NN * 2;
    const float* bias = conv_b + (size_t)(b * 3 + layer) * 128;
    float* out = xsb + (size_t)(b * 3 + layer) * SZ;

    int p0 = indptr[w], p1 = indptr[w + 1];
    float ad0 = adst[2 * w], ad1 = adst[2 * w + 1];

    float m0 = -1e30f, m1 = -1e30f;
    for (int j = p0 + lane; j < p1; j += 32) {
        int s = colsrc[j];
        float e0 = asrc[2 * s] + ad0;     e0 = e0 > 0.f ? e0 : 0.2f * e0;
        float e1 = asrc[2 * s + 1] + ad1; e1 = e1 > 0.f ? e1 : 0.2f * e1;
        m0 = fmaxf(m0, e0); m1 = fmaxf(m1, e1);
    }
    m0 = warp_max(m0); m1 = warp_max(m1);

    float z0 = 0.f, z1 = 0.f;
    for (int j = p0 + lane; j < p1; j += 32) {
        int s = colsrc[j];
        float e0 = asrc[2 * s] + ad0;     e0 = e0 > 0.f ? e0 : 0.2f * e0;
        float e1 = asrc[2 * s + 1] + ad1; e1 = e1 > 0.f ? e1 : 0.2f * e1;
        z0 += expf(e0 - m0); z1 += expf(e1 - m1);
    }
    z0 = warp_sum(z0) + 1e-16f; z1 = warp_sum(z1) + 1e-16f;
    float inv0 = 1.f / z0, inv1 = 1.f / z1;

    float acc[8];
    #pragma unroll
    for (int k = 0; k < 8; k++) acc[k] = 0.f;
    for (int j = p0; j < p1; j++) {
        int s = colsrc[j];
        float e0 = asrc[2 * s] + ad0;     e0 = e0 > 0.f ? e0 : 0.2f * e0;
        float e1 = asrc[2 * s + 1] + ad1; e1 = e1 > 0.f ? e1 : 0.2f * e1;
        float w0 = expf(e0 - m0) * inv0;
        float w1 = expf(e1 - m1) * inv1;
        const float* xr = xh + (size_t)s * 256;
        #pragma unroll
        for (int k = 0; k < 4; k++) {
            acc[k]     += w0 * xr[lane + 32 * k];
            acc[4 + k] += w1 * xr[128 + lane + 32 * k];
        }
    }
    #pragma unroll
    for (int k = 0; k < 4; k++) {
        int c = lane + 32 * k;
        float v = 0.5f * (acc[k] + acc[4 + k]) + bias[c];
        v = v > 0.f ? v : 0.f;
        out[(size_t)w * 128 + c] = v + meanb[(size_t)w * 128 + c];
    }
}

// ---------------- LSTM cell + fused JK logit (warp/node, batched z=4) --------
struct LstmArgs {
    const float* G[4];    // gates [NN][768]
    const float* bs[4];   // bias sum [768]
    const float* cp[4];   // c_prev (or null)
    float* co[4];         // c out
    float* ho[4];         // h out [NN][192]
    const float* aw[4];   // jk att weight slice [192]
    float* lg[4];         // logit out [NN]
};
__global__ void k_lstm(LstmArgs P, int N) {
    int bd = blockIdx.y;
    int w = (blockIdx.x * blockDim.x + threadIdx.x) >> 5;
    int lane = threadIdx.x & 31;
    if (w >= N) return;
    const float* g = P.G[bd] + (size_t)w * 768;
    const float* bsum = P.bs[bd];
    const float* cp = P.cp[bd];
    float* co = P.co[bd] + (size_t)w * 192;
    float* ho = P.ho[bd] + (size_t)w * 192;
    const float* aw = P.aw[bd];
    const float* cpr = cp ? cp + (size_t)w * 192 : nullptr;
    float dot = 0.f;
    #pragma unroll
    for (int it = 0; it < 6; it++) {
        int j = lane + 32 * it;
        float gi = g[j]       + bsum[j];
        float gf = g[192 + j] + bsum[192 + j];
        float gg = g[384 + j] + bsum[384 + j];
        float go = g[576 + j] + bsum[576 + j];
        float c0 = cpr ? cpr[j] : 0.f;
        float c = sigm(gf) * c0 + sigm(gi) * tanhf(gg);
        co[j] = c;
        float h = sigm(go) * tanhf(c);
        ho[j] = h;
        dot += h * aw[j];
    }
    dot = warp_sum(dot);
    if (lane == 0) P.lg[bd][w] = dot;
}

// ---------------- JK attention from precomputed logits -----------------------
__global__ void k_jk(const float* __restrict__ LOG, const float* __restrict__ jk_b,
                     const float* __restrict__ xsb, float* __restrict__ jkb, int N) {
    int b = blockIdx.y;
    int w = (blockIdx.x * blockDim.x + threadIdx.x) >> 5;
    int lane = threadIdx.x & 31;
    if (w >= N) return;
    float bb = jk_b[b];
    float a[3];
    #pragma unroll
    for (int l = 0; l < 3; l++)
        a[l] = LOG[(size_t)((b * 2 + 0) * 3 + l) * NN + w] +
               LOG[(size_t)((b * 2 + 1) * 3 + l) * NN + w] + bb;
    float m = fmaxf(a[0], fmaxf(a[1], a[2]));
    float e0 = expf(a[0] - m), e1 = expf(a[1] - m), e2 = expf(a[2] - m);
    float inv = 1.f / (e0 + e1 + e2);
    e0 *= inv; e1 *= inv; e2 *= inv;
    const float* xs0 = xsb + (size_t)(b * 3 + 0) * SZ;
    const float* xs1 = xsb + (size_t)(b * 3 + 1) * SZ;
    const float* xs2 = xsb + (size_t)(b * 3 + 2) * SZ;
    float* jk = jkb + (size_t)b * SZ;
    #pragma unroll
    for (int k = 0; k < 4; k++) {
        size_t o = (size_t)w * 128 + lane + 32 * k;
        jk[o] = xs0[o] * e0 + xs1[o] * e1 + xs2[o] * e2;
    }
}

// ---------------- final 4-way attention fusion --------------------------------
__global__ void k_final(const float* __restrict__ outs, const float* __restrict__ lw,
                        float* __restrict__ out, int N) {
    int w = (blockIdx.x * blockDim.x + threadIdx.x) >> 5;
    int lane = threadIdx.x & 31;
    if (w >= N) return;
    float s[4];
    #pragma unroll
    for (int i = 0; i < 4; i++) {
        const float* p = outs + (size_t)i * SZ + (size_t)w * 128;
        float t = 0.f;
        #pragma unroll
        for (int c = lane; c < 128; c += 32) t += p[c] * lw[c];
        s[i] = warp_sum(t);
    }
    float m = fmaxf(fmaxf(s[0], s[1]), fmaxf(s[2], s[3]));
    float e[4]; float z = 0.f;
    #pragma unroll
    for (int i = 0; i < 4; i++) { e[i] = expf(s[i] - m); z += e[i]; }
    float inv = 1.f / z;
    #pragma unroll
    for (int k = 0; k < 4; k++) {
        int c = lane + 32 * k;
        float v = 0.f;
        #pragma unroll
        for (int i = 0; i < 4; i++) v += e[i] * inv * outs[(size_t)i * SZ + (size_t)w * 128 + c];
        out[(size_t)w * 128 + c] = v;
    }
}

// ---------------- host orchestration -----------------------------------------
static inline void launch_gemm(const Ptrs12& P, int nz, int M, int Nc, int K,
                               int acc, int split) {
    dim3 g((M + 127) / 128, Nc / 128, nz), b(256);
    if (split) k_gemm<1><<<g, b>>>(P, M, Nc, K, acc);
    else       k_gemm<0><<<g, b>>>(P, M, Nc, K, acc);
}

extern "C" void kernel_launch(void* const* d_in, const int* in_sizes, int n_in,
                              void* d_out, int out_size) {
    const int*   x_idx   = (const int*)d_in[0];
    const float* x_flt   = (const float*)d_in[1];
    const int*   ei_l    = (const int*)d_in[2];
    const int*   ei_r    = (const int*)d_in[3];
    const float* emb_aa  = (const float*)d_in[4];
    const float* emb_ss  = (const float*)d_in[5];
    const float* conv_W  = (const float*)d_in[6];
    const float* att_src = (const float*)d_in[7];
    const float* att_dst = (const float*)d_in[8];
    const float* conv_b  = (const float*)d_in[9];
    const float* Wih     = (const float*)d_in[10];
    const float* Whh     = (const float*)d_in[11];
    const float* bih     = (const float*)d_in[12];
    const float* bhh     = (const float*)d_in[13];
    const float* jkW     = (const float*)d_in[14];
    const float* jkB     = (const float*)d_in[15];
    const float* dW      = (const float*)d_in[16];
    const float* dB      = (const float*)d_in[17];
    const float* fW      = (const float*)d_in[18];
    const float* fB      = (const float*)d_in[19];
    const float* lW      = (const float*)d_in[20];
    float* out = (float*)d_out;
    (void)in_sizes; (void)n_in; (void)out_size;

    float* fp = nullptr; int* ip = nullptr;
    cudaGetSymbolAddress((void**)&fp, g_fpool);
    cudaGetSymbolAddress((void**)&ip, g_ipool);

    // Region A aliases
    float* X0   = fp + OFF_A;                 // [2][NN][128]  (GAT phase)
    float* MEAN = fp + OFF_A + 2 * SZ;        // [NN][128]
    float* XH   = fp + OFF_A + 3 * SZ;        // [2][NN][256]
    float* G4   = fp + OFF_A;                 // [4][NN][768]  (LSTM phase)
    float* JKb  = fp + OFF_A;                 // [2][NN][128]  (head phase)
    float* SQ   = fp + OFF_A + 2 * SZ;        // [2][NN][128]
    float* O4   = fp + OFF_A + 4 * SZ;        // [4][NN][128]

    float* XS   = fp + OFF_XS;                // [2][3][NN][128]
    float* HC   = fp + OFF_HC;                // [4][NN][192]
    float* CST  = fp + OFF_CST;               // [4][NN][192]
    float* LOG  = fp + OFF_LOG;               // [4*3][NN]
    float* AS   = fp + OFF_AS;
    float* AD   = fp + OFF_AD;
    float* WIHT = fp + OFF_WIHT;
    float* WHHT = fp + OFF_WHHT;
    float* BSUM = fp + OFF_BSUM;

    int* PTR = ip + IOFF_PTR;
    int* CUR = ip + IOFF_CUR;
    int* COL = ip + IOFF_COL;

    const int WB = 12500;   // warp-per-node kernels: 8 warps/block

    // node features
    k_build_x<<<NN, 128>>>(x_idx, x_flt, emb_aa, emb_ss, X0, X0 + SZ);

    // CSR both branches
    k_fill_int<<<(2 * NN + 255) / 256, 256>>>(CUR, 1, 2 * NN);
    {
        dim3 g((EE + 255) / 256, 2);
        k_hist2<<<g, 256>>>(ei_l, ei_r, CUR);
    }
    k_scan2<<<2, 1024>>>(CUR, PTR);
    k_initcur<<<(2 * NN + 255) / 256, 256>>>(PTR, CUR);
    {
        dim3 g((ENN + 255) / 256, 2);
        k_scatter2<<<g, 256>>>(ei_l, ei_r, CUR, COL);
    }

    // transposed LSTM weights + combined biases
    {
        dim3 g((768 * 128 + 255) / 256, 4);
        k_transpose<<<g, 256>>>(Wih, WIHT, 768, 128);
        dim3 g2((768 * 192 + 255) / 256, 4);
        k_transpose<<<g2, 256>>>(Whh, WHHT, 768, 192);
    }
    k_bsum<<<(3072 + 255) / 256, 256>>>(bih, bhh, BSUM, 3072);

    // GAT layers (split-tf32: errors feed output directly)
    const float* xcur[2] = { X0, X0 + SZ };
    for (int i = 0; i < 3; i++) {
        k_mean<<<(int)((SZ + 255) / 256), 256>>>(xcur[0], xcur[1], MEAN, SZ);
        Ptrs12 P = {};
        for (int b = 0; b < 2; b++) {
            P.A[b] = xcur[b];
            P.B[b] = conv_W + ((size_t)b * 3 + i) * 128 * 256;
            P.Bias[b] = nullptr;
            P.C[b] = XH + (size_t)b * NN * 256;
        }
        launch_gemm(P, 2, NN, 256, 128, 0, 1);
        {
            dim3 g(WB, 2);
            k_att<<<g, 256>>>(XH, att_src, att_dst, i, AS, AD, NN);
            k_aggr<<<g, 256>>>(PTR, COL, XH, AS, AD, conv_b, i, MEAN, XS, NN);
        }
        xcur[0] = XS + (size_t)i * SZ;
        xcur[1] = XS + (size_t)(3 + i) * SZ;
    }

    // LSTM: 3 steps, 4 (branch,direction) chains batched per launch.
    // NOTE: region A (X0/MEAN/XH) is dead now; G4 aliases it.
    for (int s = 0; s < 3; s++) {
        // Wih gate GEMMs (z=4), single-pass tf32 (error heavily damped)
        {
            Ptrs12 P = {};
            for (int bd = 0; bd < 4; bd++) {
                int b = bd >> 1, d = bd & 1;
                int si = d ? 2 - s : s;
                P.A[bd] = XS + (size_t)(b * 3 + si) * SZ;
                P.B[bd] = WIHT + (size_t)bd * 98304;
                P.Bias[bd] = nullptr;
                P.C[bd] = G4 + (size_t)bd * NN * 768;
            }
            launch_gemm(P, 4, NN, 768, 128, 0, 0);
        }
        // Whh recurrent GEMMs (z=4, accumulate)
        if (s > 0) {
            Ptrs12 P = {};
            for (int bd = 0; bd < 4; bd++) {
                P.A[bd] = HC + (size_t)bd * NN * 192;
                P.B[bd] = WHHT + (size_t)bd * 147456;
                P.Bias[bd] = nullptr;
                P.C[bd] = G4 + (size_t)bd * NN * 768;
            }
            launch_gemm(P, 4, NN, 768, 192, 1, 0);
        }
        // cell + fused JK logit
        LstmArgs L;
        for (int bd = 0; bd < 4; bd++) {
            int b = bd >> 1, d = bd & 1;
            int si = d ? 2 - s : s;
            L.G[bd]  = G4 + (size_t)bd * NN * 768;
            L.bs[bd] = BSUM + (size_t)bd * 768;
            L.cp[bd] = (s == 0) ? nullptr : CST + (size_t)bd * NN * 192;
            L.co[bd] = CST + (size_t)bd * NN * 192;
            L.ho[bd] = HC + (size_t)bd * NN * 192;
            L.aw[bd] = jkW + (size_t)b * 384 + (size_t)d * 192;
            L.lg[bd] = LOG + (size_t)(bd * 3 + si) * NN;
        }
        dim3 g(WB, 4);
        k_lstm<<<g, 256>>>(L, NN);
    }

    // JK combine (region A free again: JKb/SQ/O4 alias it)
    {
        dim3 g(WB, 2);
        k_jk<<<g, 256>>>(LOG, jkB, XS, JKb, NN);
    }

    // heads: dummy (z=2), fin (z=4), split for accuracy
    {
        Ptrs12 P = {};
        for (int b = 0; b < 2; b++) {
            P.A[b] = JKb + (size_t)b * SZ;
            P.B[b] = dW + (size_t)b * 128 * 128;
            P.Bias[b] = dB + (size_t)b * 128;
            P.C[b] = SQ + (size_t)b * SZ;
        }
        launch_gemm(P, 2, NN, 128, 128, 0, 1);
    }
    {
        const float* feats[4] = { JKb, SQ, JKb + SZ, SQ + SZ };
        Ptrs12 P = {};
        for (int i = 0; i < 4; i++) {
            P.A[i] = feats[i];
            P.B[i] = fW + (size_t)i * 128 * 128;
            P.Bias[i] = fB + (size_t)i * 128;
            P.C[i] = O4 + (size_t)i * SZ;
        }
        launch_gemm(P, 4, NN, 128, 128, 0, 1);
    }

    k_final<<<WB, 256>>>(O4, lW, out, NN);
}